// round 10
// baseline (speedup 1.0000x reference)
#include <cuda_runtime.h>

// Problem constants
#define Bn 2
#define Cn 32
#define INV8 0.3535533905932738f   // 1/(2*sqrt(2))
#define NBN 221184                 // 2 * 48^3

// Scratch (static device globals; no allocations allowed)
__device__ float g_S[Bn * Cn * 8];          // parity-class sums per (b,c)
__device__ float g_W2[Bn][Cn][8][Cn];       // [b][c][corner][o] folded weights
__device__ float g_sum[Cn];
__device__ float g_sq[Cn];

// ---------------------------------------------------------------------------
__global__ void k_zero() {
    int t = threadIdx.x;
    if (t < Bn * Cn * 8) g_S[t] = 0.f;
    if (t < Cn) { g_sum[t] = 0.f; g_sq[t] = 0.f; }
}

// ---------------------------------------------------------------------------
// Parity-class sums: S[b][c][pd*4+ph*2+pw]. Each block handles ONE (d-parity,
// h-parity) class so the per-thread accumulators are two scalar registers
// (no dynamically-indexed register array -> no local-memory spills).
// Per (b,c): 48*48 rows per class, 24 float4 per row = 55296 float4, split
// into 24 slabs of 2304 (9 iterations of 256 threads).
__global__ void __launch_bounds__(256) k_parity(const float* __restrict__ x) {
    int bc = blockIdx.y;                 // 0..63
    int cls = blockIdx.x / 24;           // dpar*2 + hpar
    int slab = blockIdx.x % 24;
    int dpar = cls >> 1, hpar = cls & 1;
    const float4* p = (const float4*)x + (size_t)bc * 221184;

    float ae = 0.f, ao = 0.f;
    int e0 = slab * 2304 + threadIdx.x;
#pragma unroll
    for (int it = 0; it < 9; it++) {
        int e = e0 + it * 256;           // index within this class's element list
        int row = e / 24;
        int pos = e - row * 24;
        int dr = row / 48;
        int hr = row - dr * 48;
        int gi = ((2 * dr + dpar) * 96 + 2 * hr + hpar) * 24 + pos;
        float4 v = p[gi];
        ae += v.x + v.z;                 // even-w
        ao += v.y + v.w;                 // odd-w
    }
#pragma unroll
    for (int s = 16; s > 0; s >>= 1) {
        ae += __shfl_xor_sync(0xffffffffu, ae, s);
        ao += __shfl_xor_sync(0xffffffffu, ao, s);
    }
    if ((threadIdx.x & 31) == 0) {
        atomicAdd(&g_S[bc * 8 + cls * 2], ae);
        atomicAdd(&g_S[bc * 8 + cls * 2 + 1], ao);
    }
}

// ---------------------------------------------------------------------------
// Band means -> channel attention MLPs -> sigmoid scales -> folded W2 weights.
// band index = sd*4 + sh*2 + sw ; band 0 = aaa(low), bands 1..7 map to
// [aad,ada,add,daa,dad,dda,ddd] (z channel = 32 + c*7 + band-1).
__global__ void k_attn(const float* __restrict__ w1_low, const float* __restrict__ w2_low,
                       const float* __restrict__ w1_high, const float* __restrict__ w2_high,
                       const float* __restrict__ w_fuse) {
    __shared__ float mean8[Bn][Cn][8];
    __shared__ float hl[Bn][2];
    __shared__ float hh[Bn][14];
    __shared__ float s_all[Bn][256];
    int tid = threadIdx.x;

    if (tid < Bn * Cn) {
        int b = tid >> 5, c = tid & 31;
        float S[8];
#pragma unroll
        for (int p = 0; p < 8; p++) S[p] = g_S[tid * 8 + p];
#pragma unroll
        for (int band = 0; band < 8; band++) {
            float m = 0.f;
#pragma unroll
            for (int p = 0; p < 8; p++)
                m += (__popc(band & p) & 1) ? -S[p] : S[p];
            mean8[b][c][band] = m * (INV8 / 110592.f);
        }
    }
    __syncthreads();

    if (tid < 4) {                       // low hidden: (B,2)
        int b = tid >> 1, r = tid & 1;
        float h = 0.f;
        for (int c = 0; c < 32; c++) h += mean8[b][c][0] * w1_low[r * 32 + c];
        hl[b][r] = fmaxf(h, 0.f);
    } else if (tid < 32) {               // high hidden: (B,14)
        int idx = tid - 4;
        int b = idx / 14, r = idx % 14;
        float h = 0.f;
        for (int j = 0; j < 224; j++)
            h += mean8[b][j / 7][1 + j % 7] * w1_high[r * 224 + j];
        hh[b][r] = fmaxf(h, 0.f);
    }
    __syncthreads();

    for (int t = tid; t < 512; t += 256) {   // sigmoid scales
        int b = t >> 8, ch = t & 255;
        float pre = 0.f;
        if (ch < 32) {
            for (int r = 0; r < 2; r++) pre += hl[b][r] * w2_low[ch * 2 + r];
        } else {
            int j = ch - 32;
            for (int r = 0; r < 14; r++) pre += hh[b][r] * w2_high[j * 14 + r];
        }
        s_all[b][ch] = 1.f / (1.f + expf(-pre));
    }
    __syncthreads();

    // W2[b][c][corner][o] = INV8 * sum_band sign(band,corner)*w_fuse[o,ch]*s[b,ch]
    for (int t = tid; t < 16384; t += 256) {
        int b = t >> 13;
        int c = (t >> 8) & 31;
        int corner = (t >> 5) & 7;
        int o = t & 31;
        float val = w_fuse[o * 256 + c] * s_all[b][c];   // band 0 (aaa)
#pragma unroll
        for (int band = 1; band < 8; band++) {
            int ch = 32 + c * 7 + band - 1;
            float term = w_fuse[o * 256 + ch] * s_all[b][ch];
            val += (__popc(band & corner) & 1) ? -term : term;
        }
        g_W2[b][c][corner][o] = val * INV8;
    }
}

// ---------------------------------------------------------------------------
// Packed fp32x2 helpers (Blackwell FFMA2 — only reachable via PTX)
__device__ __forceinline__ unsigned long long fma2(unsigned long long a,
                                                   unsigned long long b,
                                                   unsigned long long c) {
    unsigned long long d;
    asm("fma.rn.f32x2 %0, %1, %2, %3;" : "=l"(d) : "l"(a), "l"(b), "l"(c));
    return d;
}
__device__ __forceinline__ unsigned long long pack2(float lo, float hi) {
    unsigned long long r;
    asm("mov.b64 %0, {%1, %2};" : "=l"(r) : "f"(lo), "f"(hi));
    return r;
}
__device__ __forceinline__ void unpack2(unsigned long long v, float& lo, float& hi) {
    asm("mov.b64 {%0, %1}, %2;" : "=f"(lo), "=f"(hi) : "l"(v));
}

// ---------------------------------------------------------------------------
// Fused stride-2 2x2x2 conv + bias + BN-stat accumulation.
// Weight tile: 32 KB smem, layout [c][corner][o] (32 floats of o per
// (c,corner) = 8 ulonglong2). Read via LDS.128 broadcast: one ulonglong2 =
// two fp32x2 weight pairs = 4 FMA2s -> halves MIO pressure vs LDS.64.
// Each thread: 2 adjacent output-W points x all 32 o-channels.
__global__ void __launch_bounds__(256) k_conv(const float* __restrict__ x,
                                              const float* __restrict__ b_fuse,
                                              float* __restrict__ out) {
    __shared__ ulonglong2 swv[2048];     // 32 KB: [c][corner] -> 8 ulonglong2 each
    __shared__ float sb[Cn];
    __shared__ float redS[8][Cn];
    __shared__ float redQ[8][Cn];
    int tid = threadIdx.x;
    int b = blockIdx.y;
    {
        float* swf = (float*)swv;
        const float* wsrc = &g_W2[b][0][0][0];
        for (int t = tid; t < 8192; t += 256) swf[t] = wsrc[t];
        if (tid < 32) sb[tid] = b_fuse[tid];
    }
    __syncthreads();

    int P = blockIdx.x * 256 + tid;      // 0..55295 (point-pair index)
    int t24 = P % 24;                    // output-W pair (w = 2*t24, 2*t24+1)
    int h = (P / 24) % 48;
    int d = P / 1152;

    const float4* xb = (const float4*)x;
    size_t base = (((size_t)(b * 32) * 96 + 2 * d) * 96 + 2 * h) * 24 + t24;

    unsigned long long accA[16], accB[16];
#pragma unroll
    for (int i = 0; i < 16; i++) { accA[i] = 0ull; accB[i] = 0ull; }

#pragma unroll 4
    for (int c = 0; c < 32; c++) {
        const float4* p = xb + base + (size_t)c * 221184;
        float4 r00 = p[0];       // (i=0,j=0)
        float4 r01 = p[24];      // (i=0,j=1)
        float4 r10 = p[2304];    // (i=1,j=0)
        float4 r11 = p[2328];    // (i=1,j=1)
        float xA[8], xB[8];      // corner = i*4 + j*2 + k
        xA[0] = r00.x; xB[0] = r00.z;  xA[1] = r00.y; xB[1] = r00.w;
        xA[2] = r01.x; xB[2] = r01.z;  xA[3] = r01.y; xB[3] = r01.w;
        xA[4] = r10.x; xB[4] = r10.z;  xA[5] = r10.y; xB[5] = r10.w;
        xA[6] = r11.x; xB[6] = r11.z;  xA[7] = r11.y; xB[7] = r11.w;
#pragma unroll
        for (int corner = 0; corner < 8; corner++) {
            unsigned long long a2 = pack2(xA[corner], xA[corner]);
            unsigned long long b2 = pack2(xB[corner], xB[corner]);
            const ulonglong2* wq = swv + (c * 8 + corner) * 8;
#pragma unroll
            for (int q = 0; q < 8; q++) {
                ulonglong2 w = wq[q];    // LDS.128: w.x={o:4q,4q+1}, w.y={o:4q+2,4q+3}
                accA[2 * q]     = fma2(w.x, a2, accA[2 * q]);
                accB[2 * q]     = fma2(w.x, b2, accB[2 * q]);
                accA[2 * q + 1] = fma2(w.y, a2, accA[2 * q + 1]);
                accB[2 * q + 1] = fma2(w.y, b2, accB[2 * q + 1]);
            }
        }
    }

    // epilogue: bias + coalesced float2 stores + fused BN statistics
    size_t obase2 = (size_t)(b * 32) * 55296 + (size_t)d * 1152 + (size_t)h * 24 + t24;
    float2* o2 = (float2*)out;
    int warp = tid >> 5, lane = tid & 31;
#pragma unroll
    for (int op = 0; op < 16; op++) {
        float a0, a1, b0, b1;
        unpack2(accA[op], a0, a1);
        unpack2(accB[op], b0, b1);
        float bias0 = sb[2 * op], bias1 = sb[2 * op + 1];
        float zA0 = a0 + bias0, zB0 = b0 + bias0;   // channel 2op, w / w+1
        float zA1 = a1 + bias1, zB1 = b1 + bias1;   // channel 2op+1
        float2 v0; v0.x = zA0; v0.y = zB0;
        float2 v1; v1.x = zA1; v1.y = zB1;
        o2[obase2 + (size_t)(2 * op) * 55296] = v0;
        o2[obase2 + (size_t)(2 * op + 1) * 55296] = v1;
        // BN stats on pre-ReLU z
        float s0 = zA0 + zB0, q0 = zA0 * zA0 + zB0 * zB0;
        float s1 = zA1 + zB1, q1 = zA1 * zA1 + zB1 * zB1;
#pragma unroll
        for (int sh = 16; sh > 0; sh >>= 1) {
            s0 += __shfl_xor_sync(0xffffffffu, s0, sh);
            q0 += __shfl_xor_sync(0xffffffffu, q0, sh);
            s1 += __shfl_xor_sync(0xffffffffu, s1, sh);
            q1 += __shfl_xor_sync(0xffffffffu, q1, sh);
        }
        if (lane == 0) {
            redS[warp][2 * op] = s0; redQ[warp][2 * op] = q0;
            redS[warp][2 * op + 1] = s1; redQ[warp][2 * op + 1] = q1;
        }
    }
    __syncthreads();
    if (tid < 64) {
        int o = tid & 31;
        if (tid < 32) {
            float S = 0.f;
#pragma unroll
            for (int w = 0; w < 8; w++) S += redS[w][o];
            atomicAdd(&g_sum[o], S);
        } else {
            float Q = 0.f;
#pragma unroll
            for (int w = 0; w < 8; w++) Q += redQ[w][o];
            atomicAdd(&g_sq[o], Q);
        }
    }
}

// ---------------------------------------------------------------------------
// In-place BatchNorm (batch stats) + affine + ReLU.
__global__ void k_final(float* __restrict__ z, const float* __restrict__ gamma,
                        const float* __restrict__ beta) {
    int idx = blockIdx.x * 256 + threadIdx.x;   // float4 index, total 1769472
    int o = (idx / 27648) & 31;                 // 27648 float4 per (b,o) plane
    float mu = g_sum[o] * (1.f / (float)NBN);
    float var = g_sq[o] * (1.f / (float)NBN) - mu * mu;
    float inv = rsqrtf(var + 1e-5f);
    float sc = gamma[o] * inv;
    float sh = beta[o] - mu * sc;
    float4* p = (float4*)z;
    float4 v = p[idx];
    v.x = fmaxf(v.x * sc + sh, 0.f);
    v.y = fmaxf(v.y * sc + sh, 0.f);
    v.z = fmaxf(v.z * sc + sh, 0.f);
    v.w = fmaxf(v.w * sc + sh, 0.f);
    p[idx] = v;
}

// ---------------------------------------------------------------------------
extern "C" void kernel_launch(void* const* d_in, const int* in_sizes, int n_in,
                              void* d_out, int out_size) {
    const float* x       = (const float*)d_in[0];
    const float* w1_low  = (const float*)d_in[1];
    const float* w2_low  = (const float*)d_in[2];
    const float* w1_high = (const float*)d_in[3];
    const float* w2_high = (const float*)d_in[4];
    const float* w_fuse  = (const float*)d_in[5];
    const float* b_fuse  = (const float*)d_in[6];
    const float* gamma   = (const float*)d_in[7];
    const float* beta    = (const float*)d_in[8];
    float* out = (float*)d_out;

    k_zero<<<1, 512>>>();
    k_parity<<<dim3(96, 64), 256>>>(x);
    k_attn<<<1, 256>>>(w1_low, w2_low, w1_high, w2_high, w_fuse);
    k_conv<<<dim3(216, 2), 256>>>(x, b_fuse, out);
    k_final<<<6912, 256>>>(out, gamma, beta);
}

// round 11
// speedup vs baseline: 1.3521x; 1.3521x over previous
#include <cuda_runtime.h>

// Problem constants
#define Bn 2
#define Cn 32
#define INV8 0.3535533905932738f   // 1/(2*sqrt(2))
#define NBN 221184                 // 2 * 48^3

// Scratch (static device globals; no allocations allowed)
__device__ float g_part[64][4][24][2];      // parity partials [bc][cls][slab][w-par]
__device__ float g_W2[Bn][Cn][8][Cn];       // [b][c][corner][o] folded weights
__device__ float g_sum[Cn];
__device__ float g_sq[Cn];

// ---------------------------------------------------------------------------
// Parity-class sums. Each block handles ONE (d-parity, h-parity) class and one
// slab; writes its partial straight to g_part (no atomics, no pre-zero).
// Per (b,c): 48*48 rows per class, 24 float4 per row = 55296 float4, split
// into 24 slabs of 2304 (9 iterations of 256 threads).
__global__ void __launch_bounds__(256) k_parity(const float* __restrict__ x) {
    int bc = blockIdx.y;                 // 0..63
    int cls = blockIdx.x / 24;           // dpar*2 + hpar
    int slab = blockIdx.x % 24;
    int dpar = cls >> 1, hpar = cls & 1;
    const float4* p = (const float4*)x + (size_t)bc * 221184;

    float ae = 0.f, ao = 0.f;
    int e0 = slab * 2304 + threadIdx.x;
#pragma unroll
    for (int it = 0; it < 9; it++) {
        int e = e0 + it * 256;           // index within this class's element list
        int row = e / 24;
        int pos = e - row * 24;
        int dr = row / 48;
        int hr = row - dr * 48;
        int gi = ((2 * dr + dpar) * 96 + 2 * hr + hpar) * 24 + pos;
        float4 v = p[gi];
        ae += v.x + v.z;                 // even-w
        ao += v.y + v.w;                 // odd-w
    }
#pragma unroll
    for (int s = 16; s > 0; s >>= 1) {
        ae += __shfl_xor_sync(0xffffffffu, ae, s);
        ao += __shfl_xor_sync(0xffffffffu, ao, s);
    }
    __shared__ float ws[8][2];
    if ((threadIdx.x & 31) == 0) {
        ws[threadIdx.x >> 5][0] = ae;
        ws[threadIdx.x >> 5][1] = ao;
    }
    __syncthreads();
    if (threadIdx.x == 0) {
        float Se = 0.f, So = 0.f;
#pragma unroll
        for (int w = 0; w < 8; w++) { Se += ws[w][0]; So += ws[w][1]; }
        g_part[bc][cls][slab][0] = Se;
        g_part[bc][cls][slab][1] = So;
    }
}

// ---------------------------------------------------------------------------
// Slab reduce -> band means -> attention MLPs -> sigmoid scales -> folded W2.
// Also zeroes g_sum/g_sq for the conv's fused BN statistics.
// band index = sd*4 + sh*2 + sw ; band 0 = aaa(low), bands 1..7 map to
// [aad,ada,add,daa,dad,dda,ddd] (z channel = 32 + c*7 + band-1).
__global__ void k_attn(const float* __restrict__ w1_low, const float* __restrict__ w2_low,
                       const float* __restrict__ w1_high, const float* __restrict__ w2_high,
                       const float* __restrict__ w_fuse) {
    __shared__ float S_sh[64][8];        // parity sums per (b,c)
    __shared__ float mean8[Bn][Cn][8];
    __shared__ float hl[Bn][2];
    __shared__ float hh[Bn][14];
    __shared__ float s_all[Bn][256];
    int tid = threadIdx.x;

    if (tid < 32) { g_sum[tid] = 0.f; g_sq[tid] = 0.f; }

    // reduce 24 slabs: 512 (bc, parity-class) entries
    for (int t = tid; t < 512; t += 256) {
        int bc = t >> 3, k = t & 7;      // k = cls*2 + e
        int cls = k >> 1, e = k & 1;
        float s = 0.f;
#pragma unroll
        for (int sl = 0; sl < 24; sl++) s += g_part[bc][cls][sl][e];
        S_sh[bc][k] = s;
    }
    __syncthreads();

    if (tid < Bn * Cn) {
        int b = tid >> 5, c = tid & 31;
        float S[8];
#pragma unroll
        for (int p = 0; p < 8; p++) S[p] = S_sh[tid][p];
#pragma unroll
        for (int band = 0; band < 8; band++) {
            float m = 0.f;
#pragma unroll
            for (int p = 0; p < 8; p++)
                m += (__popc(band & p) & 1) ? -S[p] : S[p];
            mean8[b][c][band] = m * (INV8 / 110592.f);
        }
    }
    __syncthreads();

    if (tid < 4) {                       // low hidden: (B,2)
        int b = tid >> 1, r = tid & 1;
        float h = 0.f;
        for (int c = 0; c < 32; c++) h += mean8[b][c][0] * w1_low[r * 32 + c];
        hl[b][r] = fmaxf(h, 0.f);
    } else if (tid < 32) {               // high hidden: (B,14)
        int idx = tid - 4;
        int b = idx / 14, r = idx % 14;
        float h = 0.f;
        for (int j = 0; j < 224; j++)
            h += mean8[b][j / 7][1 + j % 7] * w1_high[r * 224 + j];
        hh[b][r] = fmaxf(h, 0.f);
    }
    __syncthreads();

    for (int t = tid; t < 512; t += 256) {   // sigmoid scales
        int b = t >> 8, ch = t & 255;
        float pre = 0.f;
        if (ch < 32) {
            for (int r = 0; r < 2; r++) pre += hl[b][r] * w2_low[ch * 2 + r];
        } else {
            int j = ch - 32;
            for (int r = 0; r < 14; r++) pre += hh[b][r] * w2_high[j * 14 + r];
        }
        s_all[b][ch] = 1.f / (1.f + expf(-pre));
    }
    __syncthreads();

    // W2[b][c][corner][o] = INV8 * sum_band sign(band,corner)*w_fuse[o,ch]*s[b,ch]
    for (int t = tid; t < 16384; t += 256) {
        int b = t >> 13;
        int c = (t >> 8) & 31;
        int corner = (t >> 5) & 7;
        int o = t & 31;
        float val = w_fuse[o * 256 + c] * s_all[b][c];   // band 0 (aaa)
#pragma unroll
        for (int band = 1; band < 8; band++) {
            int ch = 32 + c * 7 + band - 1;
            float term = w_fuse[o * 256 + ch] * s_all[b][ch];
            val += (__popc(band & corner) & 1) ? -term : term;
        }
        g_W2[b][c][corner][o] = val * INV8;
    }
}

// ---------------------------------------------------------------------------
// Packed fp32x2 helpers (Blackwell FFMA2 — only reachable via PTX)
__device__ __forceinline__ unsigned long long fma2(unsigned long long a,
                                                   unsigned long long b,
                                                   unsigned long long c) {
    unsigned long long d;
    asm("fma.rn.f32x2 %0, %1, %2, %3;" : "=l"(d) : "l"(a), "l"(b), "l"(c));
    return d;
}
__device__ __forceinline__ unsigned long long pack2(float lo, float hi) {
    unsigned long long r;
    asm("mov.b64 %0, {%1, %2};" : "=l"(r) : "f"(lo), "f"(hi));
    return r;
}
__device__ __forceinline__ void unpack2(unsigned long long v, float& lo, float& hi) {
    asm("mov.b64 {%0, %1}, %2;" : "=f"(lo), "=f"(hi) : "l"(v));
}

// ---------------------------------------------------------------------------
// Fused stride-2 2x2x2 conv + bias + BN-stat accumulation.
// Software-pipelined: the 4 x-row float4s for iteration c+1 are issued BEFORE
// the corner/FMA loop of iteration c, so the LDG long-scoreboard wait is
// covered by ~256 FMA2 + 64 LDS of independent work instead of stalling.
__global__ void __launch_bounds__(256, 2) k_conv(const float* __restrict__ x,
                                                 const float* __restrict__ b_fuse,
                                                 float* __restrict__ out) {
    __shared__ ulonglong2 swv[2048];     // 32 KB: [c][corner] -> 8 ulonglong2 each
    __shared__ float sb[Cn];
    __shared__ float redS[8][Cn];
    __shared__ float redQ[8][Cn];
    int tid = threadIdx.x;
    int b = blockIdx.y;
    {
        float* swf = (float*)swv;
        const float* wsrc = &g_W2[b][0][0][0];
        for (int t = tid; t < 8192; t += 256) swf[t] = wsrc[t];
        if (tid < 32) sb[tid] = b_fuse[tid];
    }
    __syncthreads();

    int P = blockIdx.x * 256 + tid;      // 0..55295 (point-pair index)
    int t24 = P % 24;                    // output-W pair (w = 2*t24, 2*t24+1)
    int h = (P / 24) % 48;
    int d = P / 1152;

    const float4* xb = (const float4*)x;
    size_t base = (((size_t)(b * 32) * 96 + 2 * d) * 96 + 2 * h) * 24 + t24;

    unsigned long long accA[16], accB[16];
#pragma unroll
    for (int i = 0; i < 16; i++) { accA[i] = 0ull; accB[i] = 0ull; }

    // prologue: load rows for c = 0
    float4 cur0, cur1, cur2, cur3;
    {
        const float4* p = xb + base;
        cur0 = p[0]; cur1 = p[24]; cur2 = p[2304]; cur3 = p[2328];
    }

#pragma unroll 2
    for (int c = 0; c < 32; c++) {
        // prefetch next iteration's rows (wraps to c=0 at the end; unused)
        float4 n0, n1, n2, n3;
        {
            const float4* p = xb + base + (size_t)((c + 1) & 31) * 221184;
            n0 = p[0]; n1 = p[24]; n2 = p[2304]; n3 = p[2328];
        }

        float xA[8], xB[8];              // corner = i*4 + j*2 + k
        xA[0] = cur0.x; xB[0] = cur0.z;  xA[1] = cur0.y; xB[1] = cur0.w;
        xA[2] = cur1.x; xB[2] = cur1.z;  xA[3] = cur1.y; xB[3] = cur1.w;
        xA[4] = cur2.x; xB[4] = cur2.z;  xA[5] = cur2.y; xB[5] = cur2.w;
        xA[6] = cur3.x; xB[6] = cur3.z;  xA[7] = cur3.y; xB[7] = cur3.w;
#pragma unroll
        for (int corner = 0; corner < 8; corner++) {
            unsigned long long a2 = pack2(xA[corner], xA[corner]);
            unsigned long long b2 = pack2(xB[corner], xB[corner]);
            const ulonglong2* wq = swv + (c * 8 + corner) * 8;
#pragma unroll
            for (int q = 0; q < 8; q++) {
                ulonglong2 w = wq[q];    // LDS.128: w.x={o:4q,4q+1}, w.y={o:4q+2,4q+3}
                accA[2 * q]     = fma2(w.x, a2, accA[2 * q]);
                accB[2 * q]     = fma2(w.x, b2, accB[2 * q]);
                accA[2 * q + 1] = fma2(w.y, a2, accA[2 * q + 1]);
                accB[2 * q + 1] = fma2(w.y, b2, accB[2 * q + 1]);
            }
        }
        cur0 = n0; cur1 = n1; cur2 = n2; cur3 = n3;
    }

    // epilogue: bias + coalesced float2 stores + fused BN statistics
    size_t obase2 = (size_t)(b * 32) * 55296 + (size_t)d * 1152 + (size_t)h * 24 + t24;
    float2* o2 = (float2*)out;
    int warp = tid >> 5, lane = tid & 31;
#pragma unroll
    for (int op = 0; op < 16; op++) {
        float a0, a1, b0, b1;
        unpack2(accA[op], a0, a1);
        unpack2(accB[op], b0, b1);
        float bias0 = sb[2 * op], bias1 = sb[2 * op + 1];
        float zA0 = a0 + bias0, zB0 = b0 + bias0;   // channel 2op, w / w+1
        float zA1 = a1 + bias1, zB1 = b1 + bias1;   // channel 2op+1
        float2 v0; v0.x = zA0; v0.y = zB0;
        float2 v1; v1.x = zA1; v1.y = zB1;
        o2[obase2 + (size_t)(2 * op) * 55296] = v0;
        o2[obase2 + (size_t)(2 * op + 1) * 55296] = v1;
        // BN stats on pre-ReLU z
        float s0 = zA0 + zB0, q0 = zA0 * zA0 + zB0 * zB0;
        float s1 = zA1 + zB1, q1 = zA1 * zA1 + zB1 * zB1;
#pragma unroll
        for (int sh = 16; sh > 0; sh >>= 1) {
            s0 += __shfl_xor_sync(0xffffffffu, s0, sh);
            q0 += __shfl_xor_sync(0xffffffffu, q0, sh);
            s1 += __shfl_xor_sync(0xffffffffu, s1, sh);
            q1 += __shfl_xor_sync(0xffffffffu, q1, sh);
        }
        if (lane == 0) {
            redS[warp][2 * op] = s0; redQ[warp][2 * op] = q0;
            redS[warp][2 * op + 1] = s1; redQ[warp][2 * op + 1] = q1;
        }
    }
    __syncthreads();
    if (tid < 64) {
        int o = tid & 31;
        if (tid < 32) {
            float S = 0.f;
#pragma unroll
            for (int w = 0; w < 8; w++) S += redS[w][o];
            atomicAdd(&g_sum[o], S);
        } else {
            float Q = 0.f;
#pragma unroll
            for (int w = 0; w < 8; w++) Q += redQ[w][o];
            atomicAdd(&g_sq[o], Q);
        }
    }
}

// ---------------------------------------------------------------------------
// In-place BatchNorm (batch stats) + affine + ReLU.
__global__ void k_final(float* __restrict__ z, const float* __restrict__ gamma,
                        const float* __restrict__ beta) {
    int idx = blockIdx.x * 256 + threadIdx.x;   // float4 index, total 1769472
    int o = (idx / 27648) & 31;                 // 27648 float4 per (b,o) plane
    float mu = g_sum[o] * (1.f / (float)NBN);
    float var = g_sq[o] * (1.f / (float)NBN) - mu * mu;
    float inv = rsqrtf(var + 1e-5f);
    float sc = gamma[o] * inv;
    float sh = beta[o] - mu * sc;
    float4* p = (float4*)z;
    float4 v = p[idx];
    v.x = fmaxf(v.x * sc + sh, 0.f);
    v.y = fmaxf(v.y * sc + sh, 0.f);
    v.z = fmaxf(v.z * sc + sh, 0.f);
    v.w = fmaxf(v.w * sc + sh, 0.f);
    p[idx] = v;
}

// ---------------------------------------------------------------------------
extern "C" void kernel_launch(void* const* d_in, const int* in_sizes, int n_in,
                              void* d_out, int out_size) {
    const float* x       = (const float*)d_in[0];
    const float* w1_low  = (const float*)d_in[1];
    const float* w2_low  = (const float*)d_in[2];
    const float* w1_high = (const float*)d_in[3];
    const float* w2_high = (const float*)d_in[4];
    const float* w_fuse  = (const float*)d_in[5];
    const float* b_fuse  = (const float*)d_in[6];
    const float* gamma   = (const float*)d_in[7];
    const float* beta    = (const float*)d_in[8];
    float* out = (float*)d_out;

    k_parity<<<dim3(96, 64), 256>>>(x);
    k_attn<<<1, 256>>>(w1_low, w2_low, w1_high, w2_high, w_fuse);
    k_conv<<<dim3(216, 2), 256>>>(x, b_fuse, out);
    k_final<<<6912, 256>>>(out, gamma, beta);
}